// round 15
// baseline (speedup 1.0000x reference)
#include <cuda_runtime.h>

#define FULL_MASK 0xffffffffu

// ---- device scratch (no allocations allowed; zero-initialized at load,
//      and restored to zero by the finalizing block every launch) ----
__device__ float g_stage[1024];   // per-(image,class) partial sums
__device__ int   g_count;         // completed-block counter

// ============================================================================
// Packed f32x2 helpers
// ============================================================================
__device__ __forceinline__ float2 f2fma(float2 a, float2 b, float2 c) {
    float2 d;
    asm("fma.rn.f32x2 %0, %1, %2, %3;"
        : "=l"(*reinterpret_cast<unsigned long long*>(&d))
        : "l"(*reinterpret_cast<unsigned long long*>(&a)),
          "l"(*reinterpret_cast<unsigned long long*>(&b)),
          "l"(*reinterpret_cast<unsigned long long*>(&c)));
    return d;
}
__device__ __forceinline__ float2 f2mul(float2 a, float2 b) {
    float2 d;
    asm("mul.rn.f32x2 %0, %1, %2;"
        : "=l"(*reinterpret_cast<unsigned long long*>(&d))
        : "l"(*reinterpret_cast<unsigned long long*>(&a)),
          "l"(*reinterpret_cast<unsigned long long*>(&b)));
    return d;
}
__device__ __forceinline__ float2 cmul(float2 a, float2 b) {
    return { a.x * b.x - a.y * b.y, a.x * b.y + a.y * b.x };
}

// predicated swap of two floats (compiles to SELs)
__device__ __forceinline__ void cswap1(float& u, float& v, bool p) {
    float t0 = u, t1 = v;
    u = p ? t1 : t0;
    v = p ? t0 : t1;
}

// ============================================================================
// Layout: amp(lane, r) ; register bits r[0..3] = qubits {0,1,3,6}
//                        lane bits  [0..4]    = qubits {2,4,5,7,8}
// ============================================================================

template<int TB>
__device__ __forceinline__ void ry_reg(float2* a, float c, float s) {
    const float2 c2 = { c, c }, s2 = { s, s }, ns2 = { -s, -s };
    #pragma unroll
    for (int r0 = 0; r0 < 16; ++r0) {
        if (r0 & TB) continue;
        float2 a0 = a[r0], a1 = a[r0 | TB];
        a[r0]      = f2fma(a1, ns2, f2mul(a0, c2));
        a[r0 | TB] = f2fma(a0, s2,  f2mul(a1, c2));
    }
}

template<int CB, int TB>
__device__ __forceinline__ void cx_rr(float2* a) {   // pure register permutation (free)
    #pragma unroll
    for (int r0 = 0; r0 < 16; ++r0) {
        if ((r0 & CB) && !(r0 & TB)) {
            float2 t = a[r0]; a[r0] = a[r0 | TB]; a[r0 | TB] = t;
        }
    }
}

// Rx pair update: n0 = co*t0 - i si*t1 ; n1 = co*t1 - i si*t0
__device__ __forceinline__ void crx_pair(float2& t0, float2& t1, float co, float si) {
    float2 n0 = { co * t0.x + si * t1.y, co * t0.y - si * t1.x };
    float2 n1 = { co * t1.x + si * t0.y, co * t1.y - si * t0.x };
    t0 = n0; t1 = n1;
}

template<int CB, int TB>
__device__ __forceinline__ void crx_rr(float2* a, float co, float si) {
    #pragma unroll
    for (int r0 = 0; r0 < 16; ++r0) {
        if ((r0 & CB) && !(r0 & TB)) crx_pair(a[r0], a[r0 | TB], co, si);
    }
}

// ============================================================================
// Single fused kernel. The state stays REAL through construction and the
// GF(2)-collapsed ring CX (16 shfl, 48 sel); the conv1-RZ diagonal is
// transported through the ring permutation into a shared 512-entry phase
// table built during the (latency-hidden) per-block prep.
// One warp per patch, 4 warps/block (block uniform in image b).
// ============================================================================
__global__ void __launch_bounds__(128, 9)
qcnn_kernel(const float* __restrict__ x, const float* __restrict__ w,
            const float* __restrict__ fc_w, const float* __restrict__ fc_b,
            float* __restrict__ out, int K, int ncls, int nblocks, int nout) {
    __shared__ float  s_wc[42], s_ws[42];
    __shared__ float2 s_d2[16];
    __shared__ float2 s_pA[4], s_pB[4], s_pC[4];
    __shared__ float2 s_mry0, s_mry6, s_m41;
    __shared__ float2 s_D[16 * 33];         // transported conv1-RZ diagonal
    __shared__ float  s_acc[16];
    __shared__ int    s_rank;

    const int tid  = threadIdx.x;
    const int lane = tid & 31;

    // ---- per-block table prep (NO barrier here; hidden behind circuit front) ----
    if (tid < 16) s_acc[tid] = 0.f;
    if (tid < 42) {
        float s, c; __sincosf(0.5f * w[tid], &s, &c);
        s_wc[tid] = c; s_ws[tid] = s;
    } else if (tid < 58) {          // conv2 RZ diag on {q0:b0, q3:b2, q6:b3}
        const int r = tid - 42;
        const float ang = 0.5f * (((r & 1) ? w[27] : -w[27]) + ((r & 4) ? w[28] : -w[28])
                                + ((r & 8) ? w[29] : -w[29]));
        float s, c; __sincosf(ang, &s, &c);
        s_d2[r] = { c, s };
    } else if (tid == 58) {
        float s, c; __sincosf(0.5f * (w[34] + w[36]), &s, &c); s_mry0 = { c, s };
    } else if (tid == 59) {
        float s, c; __sincosf(0.5f * (w[35] + w[37]), &s, &c); s_mry6 = { c, s };
    } else if (tid == 60) {
        float s, c; __sincosf(w[41], &s, &c); s_m41 = { c, s };   // FULL angle
    } else if (tid >= 64 && tid < 68) {   // pool1 A: bit1 -> q1 (w18), bit0 -> q2 (w19)
        const int i = tid - 64;
        float s, c; __sincosf(0.5f * (((i >> 1) & 1) * w[18] + (i & 1) * w[19]), &s, &c);
        s_pA[i] = { c, s };
    } else if (tid >= 68 && tid < 72) {   // pool1 B: bit0 -> q4 (w20), bit1 -> q5 (w21)
        const int i = tid - 68;
        float s, c; __sincosf(0.5f * ((i & 1) * w[20] + ((i >> 1) & 1) * w[21]), &s, &c);
        s_pB[i] = { c, s };
    } else if (tid >= 72 && tid < 76) {   // pool1 C: bit0 -> q7 (w22), bit1 -> q8 (w23)
        const int i = tid - 72;
        float s, c; __sincosf(0.5f * ((i & 1) * w[22] + ((i >> 1) & 1) * w[23]), &s, &c);
        s_pC[i] = { c, s };
    }

    // conv1-RZ diagonal transported through the ring permutation.
    // Original basis index o: bits 0..8 = qubits q0..q8.
    // Forward ring map: nb_k = b0^...^bk (k>=1), nb_0 = b0^X (X = parity).
    {
        const float w9v  = __ldg(w + 9),  w10v = __ldg(w + 10), w11v = __ldg(w + 11);
        const float w12v = __ldg(w + 12), w13v = __ldg(w + 13), w14v = __ldg(w + 14);
        const float w15v = __ldg(w + 15), w16v = __ldg(w + 16), w17v = __ldg(w + 17);
        #pragma unroll
        for (int j = 0; j < 4; ++j) {
            const int o = tid + (j << 7);
            const int b0 = o & 1,        b1 = (o >> 1) & 1, b2 = (o >> 2) & 1;
            const int b3 = (o >> 3) & 1, b4 = (o >> 4) & 1, b5 = (o >> 5) & 1;
            const int b6 = (o >> 6) & 1, b7 = (o >> 7) & 1, b8 = (o >> 8) & 1;
            const float ang = 0.5f * ((b0 ? w9v  : -w9v)  + (b1 ? w10v : -w10v)
                                    + (b2 ? w11v : -w11v) + (b3 ? w12v : -w12v)
                                    + (b4 ? w13v : -w13v) + (b5 ? w14v : -w14v)
                                    + (b6 ? w15v : -w15v) + (b7 ? w16v : -w16v)
                                    + (b8 ? w17v : -w17v));
            const int n1 = b0 ^ b1;
            const int n2 = n1 ^ b2;
            const int n3 = n2 ^ b3;
            const int n4 = n3 ^ b4;
            const int n5 = n4 ^ b5;
            const int n6 = n5 ^ b6;
            const int n7 = n6 ^ b7;
            const int n8 = n7 ^ b8;          // = X
            const int n0 = b0 ^ n8;
            // post-ring layout: reg bits {q0,q1,q3,q6}, lane bits {q2,q4,q5,q7,q8}
            const int nreg  = n0 | (n1 << 1) | (n3 << 2) | (n6 << 3);
            const int nlane = n2 | (n4 << 1) | (n5 << 2) | (n7 << 3) | (n8 << 4);
            float s, c; __sincosf(ang, &s, &c);
            s_D[nreg * 33 + nlane] = { c, s };
        }
    }

    // ---- per-warp circuit front (shared-free until the barrier) ----
    const int warp = (blockIdx.x << 2) | (tid >> 5);
    const int b   = warp / 676;
    const int rem = warp - b * 676;
    const int pi  = rem / 26;
    const int pj  = rem - pi * 26;
    const float* img = x + b * 784;

    // merged (encoding + conv1) RY half-angles; w[0..8] in one 128B line
    const float HALF_PI = 1.57079632679489662f;
    float cr[4], sr[4], cl[5], sl[5];
    // register qubits: q0(0,0) q1(0,1) q3(1,0) q6(2,0)
    __sincosf(img[(pi + 0) * 28 + (pj + 0)] * HALF_PI + 0.5f * __ldg(w + 0), &sr[0], &cr[0]);
    __sincosf(img[(pi + 0) * 28 + (pj + 1)] * HALF_PI + 0.5f * __ldg(w + 1), &sr[1], &cr[1]);
    __sincosf(img[(pi + 1) * 28 + (pj + 0)] * HALF_PI + 0.5f * __ldg(w + 3), &sr[2], &cr[2]);
    __sincosf(img[(pi + 2) * 28 + (pj + 0)] * HALF_PI + 0.5f * __ldg(w + 6), &sr[3], &cr[3]);
    // lane qubits: q2(0,2) q4(1,1) q5(1,2) q7(2,1) q8(2,2)
    __sincosf(img[(pi + 0) * 28 + (pj + 2)] * HALF_PI + 0.5f * __ldg(w + 2), &sl[0], &cl[0]);
    __sincosf(img[(pi + 1) * 28 + (pj + 1)] * HALF_PI + 0.5f * __ldg(w + 4), &sl[1], &cl[1]);
    __sincosf(img[(pi + 1) * 28 + (pj + 2)] * HALF_PI + 0.5f * __ldg(w + 5), &sl[2], &cl[2]);
    __sincosf(img[(pi + 2) * 28 + (pj + 1)] * HALF_PI + 0.5f * __ldg(w + 7), &sl[3], &cl[3]);
    __sincosf(img[(pi + 2) * 28 + (pj + 2)] * HALF_PI + 0.5f * __ldg(w + 8), &sl[4], &cl[4]);

    float Lp = ((lane & 1)  ? sl[0] : cl[0]) * ((lane & 2)  ? sl[1] : cl[1]);
    Lp *= ((lane & 4)  ? sl[2] : cl[2]);
    Lp *= ((lane & 8)  ? sl[3] : cl[3]);
    Lp *= ((lane & 16) ? sl[4] : cl[4]);

    const float p01[4] = { cr[0]*cr[1], sr[0]*cr[1], cr[0]*sr[1], sr[0]*sr[1] };
    const float p23[4] = { cr[2]*cr[3]*Lp, sr[2]*cr[3]*Lp, cr[2]*sr[3]*Lp, sr[2]*sr[3]*Lp };

    // REAL product state
    float ar[16];
    #pragma unroll
    for (int r = 0; r < 16; ++r) ar[r] = p01[r & 3] * p23[r >> 2];

    // ---- ring CX composite as one GF(2) permutation, on REAL values ----
    {
        const bool e = (((lane >> 3) ^ (lane >> 4)) & 1) != 0;   // flip reg bits {0,1}
        const bool f = (lane & 1) != 0;                          // flip reg bit 2
        const bool g = (((lane >> 1) ^ (lane >> 2)) & 1) != 0;   // flip reg bit 3
        cswap1(ar[0], ar[3],  e); cswap1(ar[1], ar[2],  e);
        cswap1(ar[4], ar[7],  e); cswap1(ar[5], ar[6],  e);
        cswap1(ar[8], ar[11], e); cswap1(ar[9], ar[10], e);
        cswap1(ar[12],ar[15], e); cswap1(ar[13],ar[14], e);
        cswap1(ar[0], ar[4],  f); cswap1(ar[1], ar[5],  f);
        cswap1(ar[2], ar[6],  f); cswap1(ar[3], ar[7],  f);
        cswap1(ar[8], ar[12], f); cswap1(ar[9], ar[13], f);
        cswap1(ar[10],ar[14], f); cswap1(ar[11],ar[15], f);
        cswap1(ar[0], ar[8],  g); cswap1(ar[1], ar[9],  g);
        cswap1(ar[2], ar[10], g); cswap1(ar[3], ar[11], g);
        cswap1(ar[4], ar[12], g); cswap1(ar[5], ar[13], g);
        cswap1(ar[6], ar[14], g); cswap1(ar[7], ar[15], g);

        const int basev = lane ^ ((lane & 2) << 1) ^ ((lane & 8) << 1);
        const int perm[16] = {0,3,6,5,12,15,10,9,11,8,13,14,7,4,1,2};
        const int csrc[16] = {0,0,1,1,2,2,3,3,8,8,9,9,10,10,11,11};
        float bn[16];
        #pragma unroll
        for (int r = 0; r < 16; ++r)
            bn[r] = __shfl_sync(FULL_MASK, ar[perm[r]], basev ^ csrc[r]);
        #pragma unroll
        for (int r = 0; r < 16; ++r) ar[r] = bn[r];
    }

    __syncthreads();   // prep tables ready; latency hidden behind the above

    // ---- apply transported conv1-RZ diagonal: complexify ----
    float2 a[16];
    #pragma unroll
    for (int r = 0; r < 16; ++r) {
        const float2 d = s_D[r * 33 + lane];
        a[r] = { ar[r] * d.x, ar[r] * d.y };
    }

    // ---- pool1: 6 CRX merged into 3 passes ----
    {   // A: target q0 (bit0); controls q1 = reg bit1, q2 = lane bit0
        const float2 cA0 = s_pA[lane & 1];
        const float2 cA1 = s_pA[2 + (lane & 1)];
        #pragma unroll
        for (int r0 = 0; r0 < 16; r0 += 2) {
            const float2 cs = (r0 & 2) ? cA1 : cA0;
            crx_pair(a[r0], a[r0 + 1], cs.x, cs.y);
        }
    }
    {   // B: target q3 (bit2); controls q4 = lane bit1, q5 = lane bit2
        const float2 cs = s_pB[(lane >> 1) & 3];
        #pragma unroll
        for (int r0 = 0; r0 < 16; ++r0)
            if (!(r0 & 4)) crx_pair(a[r0], a[r0 | 4], cs.x, cs.y);
    }
    {   // C: target q6 (bit3); controls q7 = lane bit3, q8 = lane bit4
        const float2 cs = s_pC[(lane >> 3) & 3];
        #pragma unroll
        for (int r0 = 0; r0 < 8; ++r0) crx_pair(a[r0], a[r0 | 8], cs.x, cs.y);
    }

    // ---- conv2 on {0,3,6}: register-local ----
    ry_reg<1>(a, s_wc[24], s_ws[24]);
    ry_reg<4>(a, s_wc[25], s_ws[25]);
    ry_reg<8>(a, s_wc[26], s_ws[26]);
    #pragma unroll
    for (int r = 0; r < 16; ++r) a[r] = cmul(a[r], s_d2[r]);
    cx_rr<1, 4>(a);            // (0,3)
    cx_rr<4, 8>(a);            // (3,6)
    cx_rr<8, 1>(a);            // (6,0)
    ry_reg<1>(a, s_wc[30], s_ws[30]);
    // RZ(3, w31) dropped: commutes to the end, unobservable on q0.

    // ---- pool2 ----
    crx_rr<4, 1>(a, s_wc[32], s_ws[32]);   // (3,0)
    crx_rr<4, 8>(a, s_wc[33], s_ws[33]);   // (3,6)
    {
        const float2 m0 = s_mry0; ry_reg<1>(a, m0.x, m0.y);   // RY(0, w34+w36)
        const float2 m6 = s_mry6; ry_reg<8>(a, m6.x, m6.y);   // RY(6, w35+w37)
    }

    // ---- conv3 ----
    cx_rr<1, 8>(a);            // (0,6)
    {   // RZ(0, w38) on register bit 0
        const float cz = s_wc[38], sz = s_ws[38];
        #pragma unroll
        for (int r = 0; r < 16; ++r) {
            const float d = (r & 1) ? sz : -sz;
            const float2 v = a[r];
            a[r] = { cz * v.x - d * v.y, cz * v.y + d * v.x };
        }
    }
    // RZ(6, w39) dropped.

    // ---- pool3 CRX(6,0) ----
    crx_rr<8, 1>(a, s_wc[40], s_ws[40]);
    // Final RY(0, w41) folded into measurement (Bloch rotation below).

    // ---- <X>,<Y>,<Z> on qubit 0 ; ez via norm conservation ----
    float zr = 0.f, zi = 0.f, nz = 0.f;
    #pragma unroll
    for (int r0 = 0; r0 < 16; r0 += 2) {
        float2 a0 = a[r0], a1 = a[r0 + 1];
        zr += a0.x * a1.x + a0.y * a1.y;
        zi += a0.x * a1.y - a0.y * a1.x;
        nz += a0.x * a0.x + a0.y * a0.y;   // |a0|^2 only; ez = 2*nz - 1
    }
    #pragma unroll
    for (int off = 16; off; off >>= 1) {
        zr += __shfl_xor_sync(FULL_MASK, zr, off);
        zi += __shfl_xor_sync(FULL_MASK, zi, off);
        nz += __shfl_xor_sync(FULL_MASK, nz, off);
    }

    // ---- fused FC: lanes 0..ncls-1 stage class partials in smem ----
    if (lane < ncls) {
        const float ez = 2.f * nz - 1.f;
        // Bloch rotation for RY(w41): ex' = c*ex + s*ez ; ez' = -s*ex + c*ez
        const float2 m = s_m41;
        const float ex0 = 2.f * zr, ey = 2.f * zi;
        const float ex = m.x * ex0 + m.y * ez;
        const float ezf = -m.y * ex0 + m.x * ez;
        const float* wrow = fc_w + lane * K + rem * 3;
        const float partial = ex * wrow[0] + ey * wrow[1] + ezf * wrow[2];
        atomicAdd(&s_acc[lane], partial);
    }
    __syncthreads();

    // ---- stage into device scratch, then last-finishing block finalizes ----
    if (tid < ncls) {
        const int b_blk = (blockIdx.x << 2) / 676;   // b is block-uniform
        atomicAdd(&g_stage[b_blk * ncls + tid], s_acc[tid]);
        __threadfence();
    }
    __syncthreads();
    if (tid == 0) s_rank = atomicAdd(&g_count, 1);
    __syncthreads();

    if (s_rank == nblocks - 1) {   // all other blocks' stage atomics are visible
        __threadfence();
        for (int i = tid; i < nout; i += blockDim.x) {
            out[i] = g_stage[i] + fc_b[i % ncls];
            g_stage[i] = 0.f;      // restore invariant for next launch/replay
        }
        if (tid == 0) g_count = 0;
    }
}

// ============================================================================
extern "C" void kernel_launch(void* const* d_in, const int* in_sizes, int n_in,
                              void* d_out, int out_size) {
    const float* x    = (const float*)d_in[0];   // (B,1,28,28)
    const float* w    = (const float*)d_in[1];   // (42,)
    const float* fc_w = (const float*)d_in[2];   // (ncls, K)
    const float* fc_b = (const float*)d_in[3];   // (ncls,)
    float* out = (float*)d_out;

    const int B      = in_sizes[0] / (28 * 28);
    const int npatch = B * 26 * 26;              // 676 % 4 == 0 -> exact grid
    const int ncls   = in_sizes[3];
    const int K      = in_sizes[2] / ncls;
    const int nblocks = npatch / 4;

    qcnn_kernel<<<nblocks, 128>>>(x, w, fc_w, fc_b, out, K, ncls, nblocks, B * ncls);
}

// round 16
// speedup vs baseline: 1.0022x; 1.0022x over previous
#include <cuda_runtime.h>

#define FULL_MASK 0xffffffffu

// ---- device scratch (no allocations allowed; zero-initialized at load,
//      and restored to zero by the finalizing block every launch) ----
__device__ float g_stage[1024];   // per-(image,class) partial sums
__device__ int   g_count;         // completed-block counter

// ============================================================================
// Packed f32x2 helpers
// ============================================================================
__device__ __forceinline__ float2 f2fma(float2 a, float2 b, float2 c) {
    float2 d;
    asm("fma.rn.f32x2 %0, %1, %2, %3;"
        : "=l"(*reinterpret_cast<unsigned long long*>(&d))
        : "l"(*reinterpret_cast<unsigned long long*>(&a)),
          "l"(*reinterpret_cast<unsigned long long*>(&b)),
          "l"(*reinterpret_cast<unsigned long long*>(&c)));
    return d;
}
__device__ __forceinline__ float2 f2mul(float2 a, float2 b) {
    float2 d;
    asm("mul.rn.f32x2 %0, %1, %2;"
        : "=l"(*reinterpret_cast<unsigned long long*>(&d))
        : "l"(*reinterpret_cast<unsigned long long*>(&a)),
          "l"(*reinterpret_cast<unsigned long long*>(&b)));
    return d;
}
__device__ __forceinline__ float2 cmul(float2 a, float2 b) {
    return { a.x * b.x - a.y * b.y, a.x * b.y + a.y * b.x };
}

// predicated swap of two floats (compiles to SELs)
__device__ __forceinline__ void cswap1(float& u, float& v, bool p) {
    float t0 = u, t1 = v;
    u = p ? t1 : t0;
    v = p ? t0 : t1;
}

// ============================================================================
// Layout: amp(lane, r) ; register bits r[0..3] = qubits {0,1,3,6}
//                        lane bits  [0..4]    = qubits {2,4,5,7,8}
// ============================================================================

template<int TB>
__device__ __forceinline__ void ry_reg(float2* a, float c, float s) {
    const float2 c2 = { c, c }, s2 = { s, s }, ns2 = { -s, -s };
    #pragma unroll
    for (int r0 = 0; r0 < 16; ++r0) {
        if (r0 & TB) continue;
        float2 a0 = a[r0], a1 = a[r0 | TB];
        a[r0]      = f2fma(a1, ns2, f2mul(a0, c2));
        a[r0 | TB] = f2fma(a0, s2,  f2mul(a1, c2));
    }
}

template<int CB, int TB>
__device__ __forceinline__ void cx_rr(float2* a) {   // pure register permutation (free)
    #pragma unroll
    for (int r0 = 0; r0 < 16; ++r0) {
        if ((r0 & CB) && !(r0 & TB)) {
            float2 t = a[r0]; a[r0] = a[r0 | TB]; a[r0 | TB] = t;
        }
    }
}

// Rx pair update: n0 = co*t0 - i si*t1 ; n1 = co*t1 - i si*t0
__device__ __forceinline__ void crx_pair(float2& t0, float2& t1, float co, float si) {
    float2 n0 = { co * t0.x + si * t1.y, co * t0.y - si * t1.x };
    float2 n1 = { co * t1.x + si * t0.y, co * t1.y - si * t0.x };
    t0 = n0; t1 = n1;
}

template<int CB, int TB>
__device__ __forceinline__ void crx_rr(float2* a, float co, float si) {
    #pragma unroll
    for (int r0 = 0; r0 < 16; ++r0) {
        if ((r0 & CB) && !(r0 & TB)) crx_pair(a[r0], a[r0 | TB], co, si);
    }
}

// ============================================================================
// Single fused kernel. REAL state through construction + GF(2)-collapsed ring
// (16 shfl, 48 sel); conv1-RZ diagonal transported into a shared phase table.
// 10 blocks/SM -> 1352 blocks fit in ONE wave (148*10 = 1480).
// One warp per patch, 4 warps/block (block uniform in image b).
// ============================================================================
__global__ void __launch_bounds__(128, 10)
qcnn_kernel(const float* __restrict__ x, const float* __restrict__ w,
            const float* __restrict__ fc_w, const float* __restrict__ fc_b,
            float* __restrict__ out, int K, int ncls, int nblocks, int nout) {
    __shared__ float  s_wc[42], s_ws[42];
    __shared__ float2 s_d2[16];
    __shared__ float2 s_pA[4], s_pB[4], s_pC[4];
    __shared__ float2 s_mry0, s_mry6, s_m41;
    __shared__ float2 s_D[16 * 33];         // transported conv1-RZ diagonal
    __shared__ float  s_acc[16];
    __shared__ int    s_rank;

    const int tid  = threadIdx.x;
    const int lane = tid & 31;

    // ---- per-block table prep (NO barrier here; hidden behind circuit front) ----
    if (tid < 16) s_acc[tid] = 0.f;
    if (tid < 42) {
        float s, c; __sincosf(0.5f * w[tid], &s, &c);
        s_wc[tid] = c; s_ws[tid] = s;
    } else if (tid < 58) {          // conv2 RZ diag on {q0:b0, q3:b2, q6:b3}
        const int r = tid - 42;
        const float ang = 0.5f * (((r & 1) ? w[27] : -w[27]) + ((r & 4) ? w[28] : -w[28])
                                + ((r & 8) ? w[29] : -w[29]));
        float s, c; __sincosf(ang, &s, &c);
        s_d2[r] = { c, s };
    } else if (tid == 58) {
        float s, c; __sincosf(0.5f * (w[34] + w[36]), &s, &c); s_mry0 = { c, s };
    } else if (tid == 59) {
        float s, c; __sincosf(0.5f * (w[35] + w[37]), &s, &c); s_mry6 = { c, s };
    } else if (tid == 60) {
        float s, c; __sincosf(w[41], &s, &c); s_m41 = { c, s };   // FULL angle
    } else if (tid >= 64 && tid < 68) {   // pool1 A: bit1 -> q1 (w18), bit0 -> q2 (w19)
        const int i = tid - 64;
        float s, c; __sincosf(0.5f * (((i >> 1) & 1) * w[18] + (i & 1) * w[19]), &s, &c);
        s_pA[i] = { c, s };
    } else if (tid >= 68 && tid < 72) {   // pool1 B: bit0 -> q4 (w20), bit1 -> q5 (w21)
        const int i = tid - 68;
        float s, c; __sincosf(0.5f * ((i & 1) * w[20] + ((i >> 1) & 1) * w[21]), &s, &c);
        s_pB[i] = { c, s };
    } else if (tid >= 72 && tid < 76) {   // pool1 C: bit0 -> q7 (w22), bit1 -> q8 (w23)
        const int i = tid - 72;
        float s, c; __sincosf(0.5f * ((i & 1) * w[22] + ((i >> 1) & 1) * w[23]), &s, &c);
        s_pC[i] = { c, s };
    }

    // conv1-RZ diagonal transported through the ring permutation.
    // Original basis index o: bits 0..8 = qubits q0..q8.
    // Forward ring map: nb_k = b0^...^bk (k>=1), nb_0 = b0^X (X = parity).
    {
        const float w9v  = __ldg(w + 9),  w10v = __ldg(w + 10), w11v = __ldg(w + 11);
        const float w12v = __ldg(w + 12), w13v = __ldg(w + 13), w14v = __ldg(w + 14);
        const float w15v = __ldg(w + 15), w16v = __ldg(w + 16), w17v = __ldg(w + 17);
        #pragma unroll
        for (int j = 0; j < 4; ++j) {
            const int o = tid + (j << 7);
            const int b0 = o & 1,        b1 = (o >> 1) & 1, b2 = (o >> 2) & 1;
            const int b3 = (o >> 3) & 1, b4 = (o >> 4) & 1, b5 = (o >> 5) & 1;
            const int b6 = (o >> 6) & 1, b7 = (o >> 7) & 1, b8 = (o >> 8) & 1;
            const float ang = 0.5f * ((b0 ? w9v  : -w9v)  + (b1 ? w10v : -w10v)
                                    + (b2 ? w11v : -w11v) + (b3 ? w12v : -w12v)
                                    + (b4 ? w13v : -w13v) + (b5 ? w14v : -w14v)
                                    + (b6 ? w15v : -w15v) + (b7 ? w16v : -w16v)
                                    + (b8 ? w17v : -w17v));
            const int n1 = b0 ^ b1;
            const int n2 = n1 ^ b2;
            const int n3 = n2 ^ b3;
            const int n4 = n3 ^ b4;
            const int n5 = n4 ^ b5;
            const int n6 = n5 ^ b6;
            const int n7 = n6 ^ b7;
            const int n8 = n7 ^ b8;          // = X
            const int n0 = b0 ^ n8;
            // post-ring layout: reg bits {q0,q1,q3,q6}, lane bits {q2,q4,q5,q7,q8}
            const int nreg  = n0 | (n1 << 1) | (n3 << 2) | (n6 << 3);
            const int nlane = n2 | (n4 << 1) | (n5 << 2) | (n7 << 3) | (n8 << 4);
            float s, c; __sincosf(ang, &s, &c);
            s_D[nreg * 33 + nlane] = { c, s };
        }
    }

    // ---- per-warp circuit front (shared-free until the barrier) ----
    const int warp = (blockIdx.x << 2) | (tid >> 5);
    const int b   = warp / 676;
    const int rem = warp - b * 676;
    const int pi  = rem / 26;
    const int pj  = rem - pi * 26;
    const float* img = x + b * 784;

    // merged (encoding + conv1) RY half-angles; w[0..8] in one 128B line
    const float HALF_PI = 1.57079632679489662f;
    float cr[4], sr[4], cl[5], sl[5];
    // register qubits: q0(0,0) q1(0,1) q3(1,0) q6(2,0)
    __sincosf(img[(pi + 0) * 28 + (pj + 0)] * HALF_PI + 0.5f * __ldg(w + 0), &sr[0], &cr[0]);
    __sincosf(img[(pi + 0) * 28 + (pj + 1)] * HALF_PI + 0.5f * __ldg(w + 1), &sr[1], &cr[1]);
    __sincosf(img[(pi + 1) * 28 + (pj + 0)] * HALF_PI + 0.5f * __ldg(w + 3), &sr[2], &cr[2]);
    __sincosf(img[(pi + 2) * 28 + (pj + 0)] * HALF_PI + 0.5f * __ldg(w + 6), &sr[3], &cr[3]);
    // lane qubits: q2(0,2) q4(1,1) q5(1,2) q7(2,1) q8(2,2)
    __sincosf(img[(pi + 0) * 28 + (pj + 2)] * HALF_PI + 0.5f * __ldg(w + 2), &sl[0], &cl[0]);
    __sincosf(img[(pi + 1) * 28 + (pj + 1)] * HALF_PI + 0.5f * __ldg(w + 4), &sl[1], &cl[1]);
    __sincosf(img[(pi + 1) * 28 + (pj + 2)] * HALF_PI + 0.5f * __ldg(w + 5), &sl[2], &cl[2]);
    __sincosf(img[(pi + 2) * 28 + (pj + 1)] * HALF_PI + 0.5f * __ldg(w + 7), &sl[3], &cl[3]);
    __sincosf(img[(pi + 2) * 28 + (pj + 2)] * HALF_PI + 0.5f * __ldg(w + 8), &sl[4], &cl[4]);

    float Lp = ((lane & 1)  ? sl[0] : cl[0]) * ((lane & 2)  ? sl[1] : cl[1]);
    Lp *= ((lane & 4)  ? sl[2] : cl[2]);
    Lp *= ((lane & 8)  ? sl[3] : cl[3]);
    Lp *= ((lane & 16) ? sl[4] : cl[4]);

    const float p01[4] = { cr[0]*cr[1], sr[0]*cr[1], cr[0]*sr[1], sr[0]*sr[1] };
    const float p23[4] = { cr[2]*cr[3]*Lp, sr[2]*cr[3]*Lp, cr[2]*sr[3]*Lp, sr[2]*sr[3]*Lp };

    // REAL product state
    float ar[16];
    #pragma unroll
    for (int r = 0; r < 16; ++r) ar[r] = p01[r & 3] * p23[r >> 2];

    // ---- ring CX composite as one GF(2) permutation, on REAL values ----
    {
        const bool e = (((lane >> 3) ^ (lane >> 4)) & 1) != 0;   // flip reg bits {0,1}
        const bool f = (lane & 1) != 0;                          // flip reg bit 2
        const bool g = (((lane >> 1) ^ (lane >> 2)) & 1) != 0;   // flip reg bit 3
        cswap1(ar[0], ar[3],  e); cswap1(ar[1], ar[2],  e);
        cswap1(ar[4], ar[7],  e); cswap1(ar[5], ar[6],  e);
        cswap1(ar[8], ar[11], e); cswap1(ar[9], ar[10], e);
        cswap1(ar[12],ar[15], e); cswap1(ar[13],ar[14], e);
        cswap1(ar[0], ar[4],  f); cswap1(ar[1], ar[5],  f);
        cswap1(ar[2], ar[6],  f); cswap1(ar[3], ar[7],  f);
        cswap1(ar[8], ar[12], f); cswap1(ar[9], ar[13], f);
        cswap1(ar[10],ar[14], f); cswap1(ar[11],ar[15], f);
        cswap1(ar[0], ar[8],  g); cswap1(ar[1], ar[9],  g);
        cswap1(ar[2], ar[10], g); cswap1(ar[3], ar[11], g);
        cswap1(ar[4], ar[12], g); cswap1(ar[5], ar[13], g);
        cswap1(ar[6], ar[14], g); cswap1(ar[7], ar[15], g);

        const int basev = lane ^ ((lane & 2) << 1) ^ ((lane & 8) << 1);
        const int perm[16] = {0,3,6,5,12,15,10,9,11,8,13,14,7,4,1,2};
        const int csrc[16] = {0,0,1,1,2,2,3,3,8,8,9,9,10,10,11,11};
        float bn[16];
        #pragma unroll
        for (int r = 0; r < 16; ++r)
            bn[r] = __shfl_sync(FULL_MASK, ar[perm[r]], basev ^ csrc[r]);
        #pragma unroll
        for (int r = 0; r < 16; ++r) ar[r] = bn[r];
    }

    __syncthreads();   // prep tables ready; latency hidden behind the above

    // ---- apply transported conv1-RZ diagonal: complexify ----
    float2 a[16];
    #pragma unroll
    for (int r = 0; r < 16; ++r) {
        const float2 d = s_D[r * 33 + lane];
        a[r] = { ar[r] * d.x, ar[r] * d.y };
    }

    // ---- pool1: 6 CRX merged into 3 passes ----
    {   // A: target q0 (bit0); controls q1 = reg bit1, q2 = lane bit0
        const float2 cA0 = s_pA[lane & 1];
        const float2 cA1 = s_pA[2 + (lane & 1)];
        #pragma unroll
        for (int r0 = 0; r0 < 16; r0 += 2) {
            const float2 cs = (r0 & 2) ? cA1 : cA0;
            crx_pair(a[r0], a[r0 + 1], cs.x, cs.y);
        }
    }
    {   // B: target q3 (bit2); controls q4 = lane bit1, q5 = lane bit2
        const float2 cs = s_pB[(lane >> 1) & 3];
        #pragma unroll
        for (int r0 = 0; r0 < 16; ++r0)
            if (!(r0 & 4)) crx_pair(a[r0], a[r0 | 4], cs.x, cs.y);
    }
    {   // C: target q6 (bit3); controls q7 = lane bit3, q8 = lane bit4
        const float2 cs = s_pC[(lane >> 3) & 3];
        #pragma unroll
        for (int r0 = 0; r0 < 8; ++r0) crx_pair(a[r0], a[r0 | 8], cs.x, cs.y);
    }

    // ---- conv2 on {0,3,6}: register-local ----
    ry_reg<1>(a, s_wc[24], s_ws[24]);
    ry_reg<4>(a, s_wc[25], s_ws[25]);
    ry_reg<8>(a, s_wc[26], s_ws[26]);
    #pragma unroll
    for (int r = 0; r < 16; ++r) a[r] = cmul(a[r], s_d2[r]);
    cx_rr<1, 4>(a);            // (0,3)
    cx_rr<4, 8>(a);            // (3,6)
    cx_rr<8, 1>(a);            // (6,0)
    ry_reg<1>(a, s_wc[30], s_ws[30]);
    // RZ(3, w31) dropped: commutes to the end, unobservable on q0.

    // ---- pool2 ----
    crx_rr<4, 1>(a, s_wc[32], s_ws[32]);   // (3,0)
    crx_rr<4, 8>(a, s_wc[33], s_ws[33]);   // (3,6)
    {
        const float2 m0 = s_mry0; ry_reg<1>(a, m0.x, m0.y);   // RY(0, w34+w36)
        const float2 m6 = s_mry6; ry_reg<8>(a, m6.x, m6.y);   // RY(6, w35+w37)
    }

    // ---- conv3 ----
    cx_rr<1, 8>(a);            // (0,6)
    {   // RZ(0, w38) on register bit 0
        const float cz = s_wc[38], sz = s_ws[38];
        #pragma unroll
        for (int r = 0; r < 16; ++r) {
            const float d = (r & 1) ? sz : -sz;
            const float2 v = a[r];
            a[r] = { cz * v.x - d * v.y, cz * v.y + d * v.x };
        }
    }
    // RZ(6, w39) dropped.

    // ---- pool3 CRX(6,0) ----
    crx_rr<8, 1>(a, s_wc[40], s_ws[40]);
    // Final RY(0, w41) folded into measurement (Bloch rotation below).

    // ---- <X>,<Y>,<Z> on qubit 0 ; ez via norm conservation ----
    float zr = 0.f, zi = 0.f, nz = 0.f;
    #pragma unroll
    for (int r0 = 0; r0 < 16; r0 += 2) {
        float2 a0 = a[r0], a1 = a[r0 + 1];
        zr += a0.x * a1.x + a0.y * a1.y;
        zi += a0.x * a1.y - a0.y * a1.x;
        nz += a0.x * a0.x + a0.y * a0.y;   // |a0|^2 only; ez = 2*nz - 1
    }
    #pragma unroll
    for (int off = 16; off; off >>= 1) {
        zr += __shfl_xor_sync(FULL_MASK, zr, off);
        zi += __shfl_xor_sync(FULL_MASK, zi, off);
        nz += __shfl_xor_sync(FULL_MASK, nz, off);
    }

    // ---- fused FC: lanes 0..ncls-1 stage class partials in smem ----
    if (lane < ncls) {
        const float ez = 2.f * nz - 1.f;
        // Bloch rotation for RY(w41): ex' = c*ex + s*ez ; ez' = -s*ex + c*ez
        const float2 m = s_m41;
        const float ex0 = 2.f * zr, ey = 2.f * zi;
        const float ex = m.x * ex0 + m.y * ez;
        const float ezf = -m.y * ex0 + m.x * ez;
        const float* wrow = fc_w + lane * K + rem * 3;
        const float partial = ex * wrow[0] + ey * wrow[1] + ezf * wrow[2];
        atomicAdd(&s_acc[lane], partial);
    }
    __syncthreads();

    // ---- stage into device scratch, then last-finishing block finalizes ----
    if (tid < ncls) {
        const int b_blk = (blockIdx.x << 2) / 676;   // b is block-uniform
        atomicAdd(&g_stage[b_blk * ncls + tid], s_acc[tid]);
        __threadfence();
    }
    __syncthreads();
    if (tid == 0) s_rank = atomicAdd(&g_count, 1);
    __syncthreads();

    if (s_rank == nblocks - 1) {   // all other blocks' stage atomics are visible
        __threadfence();
        for (int i = tid; i < nout; i += blockDim.x) {
            out[i] = g_stage[i] + fc_b[i % ncls];
            g_stage[i] = 0.f;      // restore invariant for next launch/replay
        }
        if (tid == 0) g_count = 0;
    }
}

// ============================================================================
extern "C" void kernel_launch(void* const* d_in, const int* in_sizes, int n_in,
                              void* d_out, int out_size) {
    const float* x    = (const float*)d_in[0];   // (B,1,28,28)
    const float* w    = (const float*)d_in[1];   // (42,)
    const float* fc_w = (const float*)d_in[2];   // (ncls, K)
    const float* fc_b = (const float*)d_in[3];   // (ncls,)
    float* out = (float*)d_out;

    const int B      = in_sizes[0] / (28 * 28);
    const int npatch = B * 26 * 26;              // 676 % 4 == 0 -> exact grid
    const int ncls   = in_sizes[3];
    const int K      = in_sizes[2] / ncls;
    const int nblocks = npatch / 4;

    qcnn_kernel<<<nblocks, 128>>>(x, w, fc_w, fc_b, out, K, ncls, nblocks, B * ncls);
}